// round 11
// baseline (speedup 1.0000x reference)
#include <cuda_runtime.h>
#include <cuda_bf16.h>
#include <cuda_fp16.h>
#include <stdint.h>
#include <math.h>

#define BB 16
#define NN 2048
#define DD 128
#define HH 128

// ---------------- smem layout (16-bit elems), rows padded to 136 ------------
#define SSTR  136                       /* 128 + 8 pad -> 272B rows (17x16B)  */
#define SQH   0
#define SQL   (128 * SSTR)
#define SKH   (2 * 128 * SSTR)
#define SKL   (3 * 128 * SSTR)
#define SVH   (4 * 128 * SSTR)
#define SM_BYTES (5 * 128 * SSTR * 2)   /* 174080 */

// ---------------- scratch from projections ----------------------------------
__device__ __align__(16) __nv_bfloat16 g_qh[BB * NN * HH];  // [b][n][d] hi
__device__ __align__(16) __nv_bfloat16 g_ql[BB * NN * HH];  // [b][n][d] lo
__device__ __align__(16) __nv_bfloat16 g_kh[BB * NN * HH];  // [b][n][d] hi
__device__ __align__(16) __nv_bfloat16 g_kl[BB * NN * HH];  // [b][n][d] lo
__device__ __align__(16) __half        g_vf[BB * NN * HH];  // [b][h][n] fp16

// ---------------- warp-MMA helpers (sm_80-portable PTX) ---------------------
__device__ __forceinline__ void mma16816(float* c, const uint32_t* a, uint32_t b0, uint32_t b1) {
    asm volatile("mma.sync.aligned.m16n8k16.row.col.f32.bf16.bf16.f32 "
                 "{%0,%1,%2,%3}, {%4,%5,%6,%7}, {%8,%9}, {%0,%1,%2,%3};"
                 : "+f"(c[0]), "+f"(c[1]), "+f"(c[2]), "+f"(c[3])
                 : "r"(a[0]), "r"(a[1]), "r"(a[2]), "r"(a[3]), "r"(b0), "r"(b1));
}
__device__ __forceinline__ void mma16816h(float* c, const uint32_t* a, uint32_t b0, uint32_t b1) {
    asm volatile("mma.sync.aligned.m16n8k16.row.col.f32.f16.f16.f32 "
                 "{%0,%1,%2,%3}, {%4,%5,%6,%7}, {%8,%9}, {%0,%1,%2,%3};"
                 : "+f"(c[0]), "+f"(c[1]), "+f"(c[2]), "+f"(c[3])
                 : "r"(a[0]), "r"(a[1]), "r"(a[2]), "r"(a[3]), "r"(b0), "r"(b1));
}
__device__ __forceinline__ void ldm4(uint32_t* r, uint32_t addr) {
    asm volatile("ldmatrix.sync.aligned.m8n8.x4.shared.b16 {%0,%1,%2,%3}, [%4];"
                 : "=r"(r[0]), "=r"(r[1]), "=r"(r[2]), "=r"(r[3]) : "r"(addr));
}
__device__ __forceinline__ uint32_t smem_u32(const void* p) {
    uint32_t a;
    asm("{ .reg .u64 t; cvta.to.shared.u64 t, %1; cvt.u32.u64 %0, t; }" : "=r"(a) : "l"(p));
    return a;
}
// pack two f32 -> f16x2 (first arg -> low half)
__device__ __forceinline__ uint32_t pk_f16(float lo, float hi) {
    __half2 h = __floats2half2_rn(lo, hi);
    return *(uint32_t*)&h;
}

// bf16 two-split helpers (projection epilogue)
__device__ __forceinline__ void bsplit(float v, __nv_bfloat16& h, __nv_bfloat16& l) {
    h = __float2bfloat16(v);
    l = __float2bfloat16(v - __bfloat162float(h));
}
__device__ __forceinline__ uint32_t b2pack(__nv_bfloat16 a, __nv_bfloat16 b) {
    __nv_bfloat162 t; t.x = a; t.y = b;
    return *(uint32_t*)&t;
}

// ---- packed f32x2 helpers (projection FFMA2 path) --------------------------
#define F2FMA(acc, a, b) asm("fma.rn.f32x2 %0, %1, %2, %0;" : "+l"(acc) : "l"(a), "l"(b))
#define F2PACK(d, lo, hi) asm("mov.b64 %0, {%1, %2};" : "=l"(d) : "f"(lo), "f"(hi))
#define F2UNPACK(lo, hi, d) asm("mov.b64 {%0, %1}, %2;" : "=f"(lo), "=f"(hi) : "l"(d))

// ---------------------------------------------------------------------------
// Projection: relu(x@W + b).
// mode 0: bf16 hi+lo pair -> ohi/olo            (q, k; transposed==0 [token][h])
// mode 1: fp16 single     -> ohi (as __half*)   (v;    transposed==1 [b][h][n])
// ---------------------------------------------------------------------------
__global__ __launch_bounds__(256, 2) void proj_kernel(
    const float* __restrict__ x, const float* __restrict__ W,
    const float* __restrict__ bias,
    void* __restrict__ ohi_v, void* __restrict__ olo_v,
    int transposed, int mode)
{
    extern __shared__ float sm[];
    float* Xt = sm;            // [DD][64]
    float* Ws = sm + DD * 64;  // [DD][64]

    const int t0  = blockIdx.x * 64;
    const int h0  = blockIdx.y * 64;
    const int tid = threadIdx.x;

    #pragma unroll
    for (int it = 0; it < 8; it++) {
        int idx = tid + it * 256;
        int t   = idx & 63;
        int d4  = idx >> 6;
        float4 xv = *(const float4*)(x + (size_t)(t0 + t) * DD + 4 * d4);
        Xt[(4 * d4 + 0) * 64 + t] = xv.x;
        Xt[(4 * d4 + 1) * 64 + t] = xv.y;
        Xt[(4 * d4 + 2) * 64 + t] = xv.z;
        Xt[(4 * d4 + 3) * 64 + t] = xv.w;
    }
    #pragma unroll
    for (int it = 0; it < 8; it++) {
        int idx = tid + it * 256;
        int d   = idx >> 4;
        int h4  = idx & 15;
        *(float4*)(Ws + d * 64 + 4 * h4) = *(const float4*)(W + (size_t)d * HH + h0 + 4 * h4);
    }
    __syncthreads();

    const int tx = tid & 15;   // token dir
    const int ty = tid >> 4;   // h dir

    unsigned long long acc2[4][2];
    #pragma unroll
    for (int j = 0; j < 4; j++) { acc2[j][0] = 0ULL; acc2[j][1] = 0ULL; }

    #pragma unroll 4
    for (int d = 0; d < DD; d++) {
        float4 xv4 = *(const float4*)(Xt + d * 64 + 4 * tx);
        float4 wv4 = *(const float4*)(Ws + d * 64 + 4 * ty);
        unsigned long long xx0, xx1;
        F2PACK(xx0, xv4.x, xv4.y);
        F2PACK(xx1, xv4.z, xv4.w);
        float wa[4] = {wv4.x, wv4.y, wv4.z, wv4.w};
        #pragma unroll
        for (int j = 0; j < 4; j++) {
            unsigned long long ww;
            F2PACK(ww, wa[j], wa[j]);
            F2FMA(acc2[j][0], ww, xx0);
            F2FMA(acc2[j][1], ww, xx1);
        }
    }

    float acc[4][4];
    #pragma unroll
    for (int j = 0; j < 4; j++) {
        F2UNPACK(acc[j][0], acc[j][1], acc2[j][0]);
        F2UNPACK(acc[j][2], acc[j][3], acc2[j][1]);
    }
    #pragma unroll
    for (int j = 0; j < 4; j++) {
        float bj = bias[h0 + 4 * ty + j];
        #pragma unroll
        for (int i = 0; i < 4; i++)
            acc[j][i] = fmaxf(acc[j][i] + bj, 0.0f);
    }

    const int b_ = t0 >> 11;
    const int n0 = t0 & (NN - 1);

    if (mode == 1) {
        // fp16 single, transposed [b][h][n]  (V path)
        __half* oh = (__half*)ohi_v;
        #pragma unroll
        for (int j = 0; j < 4; j++) {
            size_t e = ((size_t)b_ * HH + h0 + 4 * ty + j) * NN + n0 + 4 * tx;
            *(uint2*)(oh + e) = make_uint2(pk_f16(acc[j][0], acc[j][1]),
                                           pk_f16(acc[j][2], acc[j][3]));
        }
        return;
    }

    __nv_bfloat16 hi[4][4], lo[4][4];
    #pragma unroll
    for (int j = 0; j < 4; j++)
        #pragma unroll
        for (int i = 0; i < 4; i++) bsplit(acc[j][i], hi[j][i], lo[j][i]);

    __nv_bfloat16* ohi = (__nv_bfloat16*)ohi_v;
    __nv_bfloat16* olo = (__nv_bfloat16*)olo_v;
    if (transposed) {
        #pragma unroll
        for (int j = 0; j < 4; j++) {
            size_t e = ((size_t)b_ * HH + h0 + 4 * ty + j) * NN + n0 + 4 * tx;
            *(uint2*)(ohi + e) = make_uint2(b2pack(hi[j][0], hi[j][1]), b2pack(hi[j][2], hi[j][3]));
            *(uint2*)(olo + e) = make_uint2(b2pack(lo[j][0], lo[j][1]), b2pack(lo[j][2], lo[j][3]));
        }
    } else {
        #pragma unroll
        for (int i = 0; i < 4; i++) {
            size_t e = (size_t)(t0 + 4 * tx + i) * HH + h0 + 4 * ty;
            *(uint2*)(ohi + e) = make_uint2(b2pack(hi[0][i], hi[1][i]), b2pack(hi[2][i], hi[3][i]));
            *(uint2*)(olo + e) = make_uint2(b2pack(lo[0][i], lo[1][i]), b2pack(lo[2][i], lo[3][i]));
        }
    }
}

// ---------------------------------------------------------------------------
// Attention via mma.sync m16n8k16.  Grid (16,16), 256 threads.
// S = QK^T: bf16 2-split (3 MMAs) — exp() amplifies S error.
// softmax: flash online row-max (masked-max via -1e30 sentinel), p in (0,1].
// PV: fp16 P x fp16 V, single MMA — 10-bit mantissa, ~8x finer than bf16.
// Warp w owns q-rows [16w,16w+16) x all 128 n; P stays in registers.
// ---------------------------------------------------------------------------
__global__ __launch_bounds__(256, 1) void attn_mma_kernel(
    const float* __restrict__ mask, float* __restrict__ out)
{
    extern __shared__ __nv_bfloat16 smb[];
    const uint32_t sb = smem_u32(smb);

    const int tid  = threadIdx.x;
    const int w    = tid >> 5;
    const int lane = tid & 31;
    const int g    = lane >> 2;        // group row 0..7
    const int q    = lane & 3;         // col pair 0..3
    const int b    = blockIdx.y;
    const int q0   = blockIdx.x * 128;

    // ---- Q hi/lo -> smem (once) ----
    #pragma unroll
    for (int it = 0; it < 8; it++) {
        int idx = tid + it * 256;
        int row = idx >> 4;
        int c16 = idx & 15;
        size_t e = (size_t)(b * NN + q0 + row) * HH + c16 * 8;
        *(uint4*)(smb + SQH + row * SSTR + c16 * 8) = *(const uint4*)(g_qh + e);
        *(uint4*)(smb + SQL + row * SSTR + c16 * 8) = *(const uint4*)(g_ql + e);
    }

    // ---- ldmatrix per-lane base addresses (bytes) ----
    const int a_row = 16 * w + (lane & 7) + ((lane >> 3) & 1) * 8;
    const int a_kof = (lane >> 4) * 8;
    const uint32_t qh_ad = sb + (uint32_t)(SQH + a_row * SSTR + a_kof) * 2;
    const uint32_t ql_ad = sb + (uint32_t)(SQL + a_row * SSTR + a_kof) * 2;
    const int b_row = (lane & 7) + ((lane >> 4) << 3);
    const int b_kof = ((lane >> 3) & 1) * 8;
    const uint32_t kh_ad = sb + (uint32_t)(SKH + b_row * SSTR + b_kof) * 2;
    const uint32_t kl_ad = sb + (uint32_t)(SKL + b_row * SSTR + b_kof) * 2;
    const uint32_t vh_ad = sb + (uint32_t)(SVH + b_row * SSTR + b_kof) * 2;
    const uint32_t TSTEP = 8 * SSTR * 2;   // byte step per n8-tile

    float oacc[16][4];
    #pragma unroll
    for (int t = 0; t < 16; t++)
        #pragma unroll
        for (int c = 0; c < 4; c++) oacc[t][c] = 0.0f;
    float lr0 = 0.0f, lr1 = 0.0f;
    float m0 = -1e30f, m1 = -1e30f;    // running row maxima

    const float* mrow0 = mask + ((size_t)b * NN + q0 + 16 * w + g) * NN + 2 * q;
    const float* mrow1 = mrow0 + 8 * NN;

    for (int kt = 0; kt < 16; kt++) {
        const int k0 = kt * 128;
        __syncthreads();
        // ---- K hi/lo + V(fp16) -> smem ----
        #pragma unroll
        for (int it = 0; it < 8; it++) {
            int idx = tid + it * 256;
            int row = idx >> 4;
            int c16 = idx & 15;
            size_t ek = (size_t)(b * NN + k0 + row) * HH + c16 * 8;
            size_t ev = ((size_t)b * HH + row) * NN + k0 + c16 * 8;
            *(uint4*)(smb + SKH + row * SSTR + c16 * 8) = *(const uint4*)(g_kh + ek);
            *(uint4*)(smb + SKL + row * SSTR + c16 * 8) = *(const uint4*)(g_kl + ek);
            *(uint4*)(smb + SVH + row * SSTR + c16 * 8) = *(const uint4*)(g_vf + ev);
        }
        __syncthreads();

        // ---- S = Q K^T (2-split: hh + hl + lh), 4-pair blocks ----
        float sacc[16][4];
        #pragma unroll
        for (int t = 0; t < 16; t++)
            #pragma unroll
            for (int c = 0; c < 4; c++) sacc[t][c] = 0.0f;

        #pragma unroll
        for (int j = 0; j < 8; j++) {
            uint32_t aH[4], aL[4];
            ldm4(aH, qh_ad + 32 * j);
            ldm4(aL, ql_ad + 32 * j);
            #pragma unroll
            for (int tb = 0; tb < 16; tb += 8) {
                uint32_t bH[4][4], bL[4][4];
                #pragma unroll
                for (int i = 0; i < 4; i++) {
                    ldm4(bH[i], kh_ad + (tb + 2 * i) * TSTEP + 32 * j);
                    ldm4(bL[i], kl_ad + (tb + 2 * i) * TSTEP + 32 * j);
                }
                #pragma unroll
                for (int i = 0; i < 4; i++) {
                    mma16816(sacc[tb + 2 * i],     aH, bH[i][0], bH[i][1]);
                    mma16816(sacc[tb + 2 * i + 1], aH, bH[i][2], bH[i][3]);
                }
                #pragma unroll
                for (int i = 0; i < 4; i++) {
                    mma16816(sacc[tb + 2 * i],     aH, bL[i][0], bL[i][1]);
                    mma16816(sacc[tb + 2 * i + 1], aH, bL[i][2], bL[i][3]);
                }
                #pragma unroll
                for (int i = 0; i < 4; i++) {
                    mma16816(sacc[tb + 2 * i],     aL, bH[i][0], bH[i][1]);
                    mma16816(sacc[tb + 2 * i + 1], aL, bH[i][2], bH[i][3]);
                }
            }
        }

        // ---- mask -> -1e30 sentinel (in place), tile row-max ----
        float tm0 = -1e30f, tm1 = -1e30f;
        #pragma unroll
        for (int t = 0; t < 16; t++) {
            float2 ma = *(const float2*)(mrow0 + k0 + 8 * t);
            float2 mb = *(const float2*)(mrow1 + k0 + 8 * t);
            float z;
            z = fmaf(ma.x, 1e30f, -1e30f); sacc[t][0] = fmaf(sacc[t][0], ma.x, z);
            z = fmaf(ma.y, 1e30f, -1e30f); sacc[t][1] = fmaf(sacc[t][1], ma.y, z);
            z = fmaf(mb.x, 1e30f, -1e30f); sacc[t][2] = fmaf(sacc[t][2], mb.x, z);
            z = fmaf(mb.y, 1e30f, -1e30f); sacc[t][3] = fmaf(sacc[t][3], mb.y, z);
            tm0 = fmaxf(tm0, fmaxf(sacc[t][0], sacc[t][1]));
            tm1 = fmaxf(tm1, fmaxf(sacc[t][2], sacc[t][3]));
        }
        tm0 = fmaxf(tm0, __shfl_xor_sync(0xffffffffu, tm0, 1));
        tm0 = fmaxf(tm0, __shfl_xor_sync(0xffffffffu, tm0, 2));
        tm1 = fmaxf(tm1, __shfl_xor_sync(0xffffffffu, tm1, 1));
        tm1 = fmaxf(tm1, __shfl_xor_sync(0xffffffffu, tm1, 2));

        // ---- online-max update + rescale (alpha=0 on first tile) ----
        float mn0 = fmaxf(m0, tm0);
        float mn1 = fmaxf(m1, tm1);
        float a0 = __expf(m0 - mn0);
        float a1 = __expf(m1 - mn1);
        m0 = mn0; m1 = mn1;
        lr0 *= a0; lr1 *= a1;
        #pragma unroll
        for (int t = 0; t < 16; t++) {
            oacc[t][0] *= a0; oacc[t][1] *= a0;
            oacc[t][2] *= a1; oacc[t][3] *= a1;
        }

        // ---- p = exp(s - m) (sentinel -> 0), pack fp16 A-frags ----
        uint32_t pfh[8][4];
        #pragma unroll
        for (int t = 0; t < 16; t++) {
            float p0 = __expf(sacc[t][0] - mn0);
            float p1 = __expf(sacc[t][1] - mn0);
            float p2 = __expf(sacc[t][2] - mn1);
            float p3 = __expf(sacc[t][3] - mn1);
            lr0 += p0 + p1;
            lr1 += p2 + p3;
            int jj = t >> 1, s = (t & 1) * 2;
            pfh[jj][s]     = pk_f16(p0, p1);
            pfh[jj][s + 1] = pk_f16(p2, p3);
        }

        // ---- O += P V (fp16 x fp16) ----
        #pragma unroll
        for (int j = 0; j < 8; j++) {
            #pragma unroll
            for (int t = 0; t < 16; t += 2) {
                uint32_t bH[4];
                ldm4(bH, vh_ad + t * TSTEP + 32 * j);
                mma16816h(oacc[t],     pfh[j], bH[0], bH[1]);
                mma16816h(oacc[t + 1], pfh[j], bH[2], bH[3]);
            }
        }
    }

    // ---- row-sum reduce within quad (cols split over 4 lanes) ----
    lr0 += __shfl_xor_sync(0xffffffffu, lr0, 1);
    lr0 += __shfl_xor_sync(0xffffffffu, lr0, 2);
    lr1 += __shfl_xor_sync(0xffffffffu, lr1, 1);
    lr1 += __shfl_xor_sync(0xffffffffu, lr1, 2);
    const float inv0 = 1.0f / lr0;
    const float inv1 = 1.0f / lr1;

    const int row0 = q0 + 16 * w + g;
    float* o0 = out + ((size_t)b * NN + row0) * HH + 2 * q;
    float* o1 = o0 + 8 * HH;
    #pragma unroll
    for (int t = 0; t < 16; t++) {
        *(float2*)(o0 + 8 * t) = make_float2(oacc[t][0] * inv0, oacc[t][1] * inv0);
        *(float2*)(o1 + 8 * t) = make_float2(oacc[t][2] * inv1, oacc[t][3] * inv1);
    }
}

// ---------------------------------------------------------------------------
extern "C" void kernel_launch(void* const* d_in, const int* in_sizes, int n_in,
                              void* d_out, int out_size)
{
    const float* x    = (const float*)d_in[0];
    const float* mask = (const float*)d_in[1];
    const float* Wv   = (const float*)d_in[2];
    const float* bv   = (const float*)d_in[3];
    const float* Wk   = (const float*)d_in[4];
    const float* bk   = (const float*)d_in[5];
    const float* Wq   = (const float*)d_in[6];
    const float* bq   = (const float*)d_in[7];
    float* out = (float*)d_out;

    void *qh, *ql, *kh, *kl, *vf;
    cudaGetSymbolAddress(&qh, g_qh);
    cudaGetSymbolAddress(&ql, g_ql);
    cudaGetSymbolAddress(&kh, g_kh);
    cudaGetSymbolAddress(&kl, g_kl);
    cudaGetSymbolAddress(&vf, g_vf);

    cudaFuncSetAttribute(proj_kernel, cudaFuncAttributeMaxDynamicSharedMemorySize, 65536);
    cudaFuncSetAttribute(attn_mma_kernel, cudaFuncAttributeMaxDynamicSharedMemorySize, SM_BYTES);

    dim3 pg(BB * NN / 64, HH / 64);
    proj_kernel<<<pg, 256, 65536>>>(x, Wv, bv, vf, vf, 1, 1);
    proj_kernel<<<pg, 256, 65536>>>(x, Wk, bk, kh, kl, 0, 0);
    proj_kernel<<<pg, 256, 65536>>>(x, Wq, bq, qh, ql, 0, 0);

    dim3 ag(NN / 128, BB);
    attn_mma_kernel<<<ag, 256, SM_BYTES>>>(mask, out);
}

// round 14
// speedup vs baseline: 1.0507x; 1.0507x over previous
#include <cuda_runtime.h>
#include <cuda_bf16.h>
#include <cuda_fp16.h>
#include <stdint.h>
#include <math.h>

#define BB 16
#define NN 2048
#define DD 128
#define HH 128

// ---------------- smem layout (16-bit elems), rows padded to 136 ------------
#define SSTR  136                       /* 128 + 8 pad -> 272B rows (17x16B)  */
#define SQH   0
#define SQL   (128 * SSTR)
#define SKH   (2 * 128 * SSTR)
#define SKL   (3 * 128 * SSTR)
#define SVH   (4 * 128 * SSTR)
#define SM_BYTES (5 * 128 * SSTR * 2)   /* 174080 */

// ---------------- scratch from projections ----------------------------------
__device__ __align__(16) __nv_bfloat16 g_qh[BB * NN * HH];  // [b][n][d] hi
__device__ __align__(16) __nv_bfloat16 g_ql[BB * NN * HH];  // [b][n][d] lo
__device__ __align__(16) __nv_bfloat16 g_kh[BB * NN * HH];  // [b][n][d] hi
__device__ __align__(16) __nv_bfloat16 g_kl[BB * NN * HH];  // [b][n][d] lo
__device__ __align__(16) __half        g_vf[BB * NN * HH];  // [b][h][n] fp16

// ---------------- warp-MMA helpers (sm_80-portable PTX) ---------------------
__device__ __forceinline__ void mma16816(float* c, const uint32_t* a, uint32_t b0, uint32_t b1) {
    asm volatile("mma.sync.aligned.m16n8k16.row.col.f32.bf16.bf16.f32 "
                 "{%0,%1,%2,%3}, {%4,%5,%6,%7}, {%8,%9}, {%0,%1,%2,%3};"
                 : "+f"(c[0]), "+f"(c[1]), "+f"(c[2]), "+f"(c[3])
                 : "r"(a[0]), "r"(a[1]), "r"(a[2]), "r"(a[3]), "r"(b0), "r"(b1));
}
__device__ __forceinline__ void mma16816h(float* c, const uint32_t* a, uint32_t b0, uint32_t b1) {
    asm volatile("mma.sync.aligned.m16n8k16.row.col.f32.f16.f16.f32 "
                 "{%0,%1,%2,%3}, {%4,%5,%6,%7}, {%8,%9}, {%0,%1,%2,%3};"
                 : "+f"(c[0]), "+f"(c[1]), "+f"(c[2]), "+f"(c[3])
                 : "r"(a[0]), "r"(a[1]), "r"(a[2]), "r"(a[3]), "r"(b0), "r"(b1));
}
__device__ __forceinline__ void ldm4(uint32_t* r, uint32_t addr) {
    asm volatile("ldmatrix.sync.aligned.m8n8.x4.shared.b16 {%0,%1,%2,%3}, [%4];"
                 : "=r"(r[0]), "=r"(r[1]), "=r"(r[2]), "=r"(r[3]) : "r"(addr));
}
__device__ __forceinline__ uint32_t smem_u32(const void* p) {
    uint32_t a;
    asm("{ .reg .u64 t; cvta.to.shared.u64 t, %1; cvt.u32.u64 %0, t; }" : "=r"(a) : "l"(p));
    return a;
}
// pack two f32 -> f16x2 (first arg -> low half)
__device__ __forceinline__ uint32_t pk_f16(float lo, float hi) {
    __half2 h = __floats2half2_rn(lo, hi);
    return *(uint32_t*)&h;
}

// bf16 two-split helpers (projection epilogue)
__device__ __forceinline__ void bsplit(float v, __nv_bfloat16& h, __nv_bfloat16& l) {
    h = __float2bfloat16(v);
    l = __float2bfloat16(v - __bfloat162float(h));
}
__device__ __forceinline__ uint32_t b2pack(__nv_bfloat16 a, __nv_bfloat16 b) {
    __nv_bfloat162 t; t.x = a; t.y = b;
    return *(uint32_t*)&t;
}

// ---- packed f32x2 helpers (projection FFMA2 path) --------------------------
#define F2FMA(acc, a, b) asm("fma.rn.f32x2 %0, %1, %2, %0;" : "+l"(acc) : "l"(a), "l"(b))
#define F2PACK(d, lo, hi) asm("mov.b64 %0, {%1, %2};" : "=l"(d) : "f"(lo), "f"(hi))
#define F2UNPACK(lo, hi, d) asm("mov.b64 {%0, %1}, %2;" : "=f"(lo), "=f"(hi) : "l"(d))

// ---------------------------------------------------------------------------
// Projection: relu(x@W + b).
// mode 0: bf16 hi+lo pair -> ohi/olo            (q, k; transposed==0 [token][h])
// mode 1: fp16 single     -> ohi (as __half*)   (v;    transposed==1 [b][h][n])
// ---------------------------------------------------------------------------
__global__ __launch_bounds__(256, 2) void proj_kernel(
    const float* __restrict__ x, const float* __restrict__ W,
    const float* __restrict__ bias,
    void* __restrict__ ohi_v, void* __restrict__ olo_v,
    int transposed, int mode)
{
    extern __shared__ float sm[];
    float* Xt = sm;            // [DD][64]
    float* Ws = sm + DD * 64;  // [DD][64]

    const int t0  = blockIdx.x * 64;
    const int h0  = blockIdx.y * 64;
    const int tid = threadIdx.x;

    #pragma unroll
    for (int it = 0; it < 8; it++) {
        int idx = tid + it * 256;
        int t   = idx & 63;
        int d4  = idx >> 6;
        float4 xv = *(const float4*)(x + (size_t)(t0 + t) * DD + 4 * d4);
        Xt[(4 * d4 + 0) * 64 + t] = xv.x;
        Xt[(4 * d4 + 1) * 64 + t] = xv.y;
        Xt[(4 * d4 + 2) * 64 + t] = xv.z;
        Xt[(4 * d4 + 3) * 64 + t] = xv.w;
    }
    #pragma unroll
    for (int it = 0; it < 8; it++) {
        int idx = tid + it * 256;
        int d   = idx >> 4;
        int h4  = idx & 15;
        *(float4*)(Ws + d * 64 + 4 * h4) = *(const float4*)(W + (size_t)d * HH + h0 + 4 * h4);
    }
    __syncthreads();

    const int tx = tid & 15;   // token dir
    const int ty = tid >> 4;   // h dir

    unsigned long long acc2[4][2];
    #pragma unroll
    for (int j = 0; j < 4; j++) { acc2[j][0] = 0ULL; acc2[j][1] = 0ULL; }

    #pragma unroll 4
    for (int d = 0; d < DD; d++) {
        float4 xv4 = *(const float4*)(Xt + d * 64 + 4 * tx);
        float4 wv4 = *(const float4*)(Ws + d * 64 + 4 * ty);
        unsigned long long xx0, xx1;
        F2PACK(xx0, xv4.x, xv4.y);
        F2PACK(xx1, xv4.z, xv4.w);
        float wa[4] = {wv4.x, wv4.y, wv4.z, wv4.w};
        #pragma unroll
        for (int j = 0; j < 4; j++) {
            unsigned long long ww;
            F2PACK(ww, wa[j], wa[j]);
            F2FMA(acc2[j][0], ww, xx0);
            F2FMA(acc2[j][1], ww, xx1);
        }
    }

    float acc[4][4];
    #pragma unroll
    for (int j = 0; j < 4; j++) {
        F2UNPACK(acc[j][0], acc[j][1], acc2[j][0]);
        F2UNPACK(acc[j][2], acc[j][3], acc2[j][1]);
    }
    #pragma unroll
    for (int j = 0; j < 4; j++) {
        float bj = bias[h0 + 4 * ty + j];
        #pragma unroll
        for (int i = 0; i < 4; i++)
            acc[j][i] = fmaxf(acc[j][i] + bj, 0.0f);
    }

    const int b_ = t0 >> 11;
    const int n0 = t0 & (NN - 1);

    if (mode == 1) {
        __half* oh = (__half*)ohi_v;
        #pragma unroll
        for (int j = 0; j < 4; j++) {
            size_t e = ((size_t)b_ * HH + h0 + 4 * ty + j) * NN + n0 + 4 * tx;
            *(uint2*)(oh + e) = make_uint2(pk_f16(acc[j][0], acc[j][1]),
                                           pk_f16(acc[j][2], acc[j][3]));
        }
        return;
    }

    __nv_bfloat16 hi[4][4], lo[4][4];
    #pragma unroll
    for (int j = 0; j < 4; j++)
        #pragma unroll
        for (int i = 0; i < 4; i++) bsplit(acc[j][i], hi[j][i], lo[j][i]);

    __nv_bfloat16* ohi = (__nv_bfloat16*)ohi_v;
    __nv_bfloat16* olo = (__nv_bfloat16*)olo_v;
    if (transposed) {
        #pragma unroll
        for (int j = 0; j < 4; j++) {
            size_t e = ((size_t)b_ * HH + h0 + 4 * ty + j) * NN + n0 + 4 * tx;
            *(uint2*)(ohi + e) = make_uint2(b2pack(hi[j][0], hi[j][1]), b2pack(hi[j][2], hi[j][3]));
            *(uint2*)(olo + e) = make_uint2(b2pack(lo[j][0], lo[j][1]), b2pack(lo[j][2], lo[j][3]));
        }
    } else {
        #pragma unroll
        for (int i = 0; i < 4; i++) {
            size_t e = (size_t)(t0 + 4 * tx + i) * HH + h0 + 4 * ty;
            *(uint2*)(ohi + e) = make_uint2(b2pack(hi[0][i], hi[1][i]), b2pack(hi[2][i], hi[3][i]));
            *(uint2*)(olo + e) = make_uint2(b2pack(lo[0][i], lo[1][i]), b2pack(lo[2][i], lo[3][i]));
        }
    }
}

// ---------------------------------------------------------------------------
// Attention via mma.sync m16n8k16.  Grid (16,16), 256 threads.
// k-tile of 128 processed as two 64-key halves (register relief):
//   S-half (bf16 2-split) -> online-softmax-half -> PV-half (fp16).
// Plain uint4 fills (cp.async removed pending container-failure isolation).
// ---------------------------------------------------------------------------
__global__ __launch_bounds__(256, 1) void attn_mma_kernel(
    const float* __restrict__ mask, float* __restrict__ out)
{
    extern __shared__ __nv_bfloat16 smb[];
    const uint32_t sb = smem_u32(smb);

    const int tid  = threadIdx.x;
    const int w    = tid >> 5;
    const int lane = tid & 31;
    const int g    = lane >> 2;        // group row 0..7
    const int q    = lane & 3;         // col pair 0..3
    const int b    = blockIdx.y;
    const int q0   = blockIdx.x * 128;

    // ---- Q hi/lo -> smem (once) ----
    #pragma unroll
    for (int it = 0; it < 8; it++) {
        int idx = tid + it * 256;
        int row = idx >> 4;
        int c16 = idx & 15;
        size_t e = (size_t)(b * NN + q0 + row) * HH + c16 * 8;
        *(uint4*)(smb + SQH + row * SSTR + c16 * 8) = *(const uint4*)(g_qh + e);
        *(uint4*)(smb + SQL + row * SSTR + c16 * 8) = *(const uint4*)(g_ql + e);
    }

    // ---- ldmatrix per-lane base addresses (bytes) ----
    const int a_row = 16 * w + (lane & 7) + ((lane >> 3) & 1) * 8;
    const int a_kof = (lane >> 4) * 8;
    const uint32_t qh_ad = sb + (uint32_t)(SQH + a_row * SSTR + a_kof) * 2;
    const uint32_t ql_ad = sb + (uint32_t)(SQL + a_row * SSTR + a_kof) * 2;
    const int b_row = (lane & 7) + ((lane >> 4) << 3);
    const int b_kof = ((lane >> 3) & 1) * 8;
    const uint32_t kh_ad = sb + (uint32_t)(SKH + b_row * SSTR + b_kof) * 2;
    const uint32_t kl_ad = sb + (uint32_t)(SKL + b_row * SSTR + b_kof) * 2;
    const uint32_t vh_ad = sb + (uint32_t)(SVH + b_row * SSTR + b_kof) * 2;
    const uint32_t TSTEP = 8 * SSTR * 2;   // byte step per n8-tile

    float oacc[16][4];
    #pragma unroll
    for (int t = 0; t < 16; t++)
        #pragma unroll
        for (int c = 0; c < 4; c++) oacc[t][c] = 0.0f;
    float lr0 = 0.0f, lr1 = 0.0f;
    float m0 = -1e30f, m1 = -1e30f;    // running row maxima

    const float* mrow0 = mask + ((size_t)b * NN + q0 + 16 * w + g) * NN + 2 * q;
    const float* mrow1 = mrow0 + 8 * NN;

    for (int kt = 0; kt < 16; kt++) {
        const int k0 = kt * 128;
        __syncthreads();   // all warps done with K/V smem of prev tile

        // ---- K hi/lo + V(fp16) -> smem (plain vector fills) ----
        #pragma unroll
        for (int it = 0; it < 8; it++) {
            int idx = tid + it * 256;
            int row = idx >> 4;
            int c16 = idx & 15;
            size_t ek = (size_t)(b * NN + k0 + row) * HH + c16 * 8;
            size_t ev = ((size_t)b * HH + row) * NN + k0 + c16 * 8;
            *(uint4*)(smb + SKH + row * SSTR + c16 * 8) = *(const uint4*)(g_kh + ek);
            *(uint4*)(smb + SKL + row * SSTR + c16 * 8) = *(const uint4*)(g_kl + ek);
            *(uint4*)(smb + SVH + row * SSTR + c16 * 8) = *(const uint4*)(g_vf + ev);
        }
        __syncthreads();

        #pragma unroll
        for (int h = 0; h < 2; h++) {
            // ---- S = Q K^T over 64 keys (2-split: hh + hl + lh) ----
            float sacc[8][4];
            #pragma unroll
            for (int t = 0; t < 8; t++)
                #pragma unroll
                for (int c = 0; c < 4; c++) sacc[t][c] = 0.0f;

            #pragma unroll
            for (int j = 0; j < 8; j++) {
                uint32_t aH[4], aL[4];
                ldm4(aH, qh_ad + 32 * j);
                ldm4(aL, ql_ad + 32 * j);
                #pragma unroll
                for (int tb = 0; tb < 8; tb += 4) {
                    uint32_t bH[2][4], bL[2][4];
                    #pragma unroll
                    for (int i = 0; i < 2; i++) {
                        ldm4(bH[i], kh_ad + (8 * h + tb + 2 * i) * TSTEP + 32 * j);
                        ldm4(bL[i], kl_ad + (8 * h + tb + 2 * i) * TSTEP + 32 * j);
                    }
                    #pragma unroll
                    for (int i = 0; i < 2; i++) {
                        mma16816(sacc[tb + 2 * i],     aH, bH[i][0], bH[i][1]);
                        mma16816(sacc[tb + 2 * i + 1], aH, bH[i][2], bH[i][3]);
                    }
                    #pragma unroll
                    for (int i = 0; i < 2; i++) {
                        mma16816(sacc[tb + 2 * i],     aH, bL[i][0], bL[i][1]);
                        mma16816(sacc[tb + 2 * i + 1], aH, bL[i][2], bL[i][3]);
                    }
                    #pragma unroll
                    for (int i = 0; i < 2; i++) {
                        mma16816(sacc[tb + 2 * i],     aL, bH[i][0], bH[i][1]);
                        mma16816(sacc[tb + 2 * i + 1], aL, bH[i][2], bH[i][3]);
                    }
                }
            }

            // ---- mask -> -1e30 sentinel (in place), tile row-max ----
            const int mko = k0 + 64 * h;
            float tm0 = -1e30f, tm1 = -1e30f;
            #pragma unroll
            for (int t = 0; t < 8; t++) {
                float2 ma = *(const float2*)(mrow0 + mko + 8 * t);
                float2 mb = *(const float2*)(mrow1 + mko + 8 * t);
                float z;
                z = fmaf(ma.x, 1e30f, -1e30f); sacc[t][0] = fmaf(sacc[t][0], ma.x, z);
                z = fmaf(ma.y, 1e30f, -1e30f); sacc[t][1] = fmaf(sacc[t][1], ma.y, z);
                z = fmaf(mb.x, 1e30f, -1e30f); sacc[t][2] = fmaf(sacc[t][2], mb.x, z);
                z = fmaf(mb.y, 1e30f, -1e30f); sacc[t][3] = fmaf(sacc[t][3], mb.y, z);
                tm0 = fmaxf(tm0, fmaxf(sacc[t][0], sacc[t][1]));
                tm1 = fmaxf(tm1, fmaxf(sacc[t][2], sacc[t][3]));
            }
            tm0 = fmaxf(tm0, __shfl_xor_sync(0xffffffffu, tm0, 1));
            tm0 = fmaxf(tm0, __shfl_xor_sync(0xffffffffu, tm0, 2));
            tm1 = fmaxf(tm1, __shfl_xor_sync(0xffffffffu, tm1, 1));
            tm1 = fmaxf(tm1, __shfl_xor_sync(0xffffffffu, tm1, 2));

            // ---- online-max update (+ warp-uniform skip of rescale) ----
            float mn0 = fmaxf(m0, tm0);
            float mn1 = fmaxf(m1, tm1);
            float a0 = __expf(m0 - mn0);
            float a1 = __expf(m1 - mn1);
            m0 = mn0; m1 = mn1;
            bool need = (a0 != 1.0f) || (a1 != 1.0f);
            if (__any_sync(0xffffffffu, need)) {
                lr0 *= a0; lr1 *= a1;
                #pragma unroll
                for (int t = 0; t < 16; t++) {
                    oacc[t][0] *= a0; oacc[t][1] *= a0;
                    oacc[t][2] *= a1; oacc[t][3] *= a1;
                }
            }

            // ---- p = exp(s - m) (sentinel -> 0), pack fp16 A-frags ----
            uint32_t pfh[4][4];
            #pragma unroll
            for (int t = 0; t < 8; t++) {
                float p0 = __expf(sacc[t][0] - mn0);
                float p1 = __expf(sacc[t][1] - mn0);
                float p2 = __expf(sacc[t][2] - mn1);
                float p3 = __expf(sacc[t][3] - mn1);
                lr0 += p0 + p1;
                lr1 += p2 + p3;
                int jj = t >> 1, s = (t & 1) * 2;
                pfh[jj][s]     = pk_f16(p0, p1);
                pfh[jj][s + 1] = pk_f16(p2, p3);
            }

            // ---- O += P V (fp16 x fp16), keys [64h, 64h+64) ----
            #pragma unroll
            for (int j = 0; j < 4; j++) {
                const uint32_t vj = vh_ad + 32 * (4 * h + j);
                #pragma unroll
                for (int t = 0; t < 16; t += 2) {
                    uint32_t bH[4];
                    ldm4(bH, vj + t * TSTEP);
                    mma16816h(oacc[t],     pfh[j], bH[0], bH[1]);
                    mma16816h(oacc[t + 1], pfh[j], bH[2], bH[3]);
                }
            }
        }
    }

    // ---- row-sum reduce within quad (cols split over 4 lanes) ----
    lr0 += __shfl_xor_sync(0xffffffffu, lr0, 1);
    lr0 += __shfl_xor_sync(0xffffffffu, lr0, 2);
    lr1 += __shfl_xor_sync(0xffffffffu, lr1, 1);
    lr1 += __shfl_xor_sync(0xffffffffu, lr1, 2);
    const float inv0 = 1.0f / lr0;
    const float inv1 = 1.0f / lr1;

    const int row0 = q0 + 16 * w + g;
    float* o0 = out + ((size_t)b * NN + row0) * HH + 2 * q;
    float* o1 = o0 + 8 * HH;
    #pragma unroll
    for (int t = 0; t < 16; t++) {
        *(float2*)(o0 + 8 * t) = make_float2(oacc[t][0] * inv0, oacc[t][1] * inv0);
        *(float2*)(o1 + 8 * t) = make_float2(oacc[t][2] * inv1, oacc[t][3] * inv1);
    }
}

// ---------------------------------------------------------------------------
extern "C" void kernel_launch(void* const* d_in, const int* in_sizes, int n_in,
                              void* d_out, int out_size)
{
    const float* x    = (const float*)d_in[0];
    const float* mask = (const float*)d_in[1];
    const float* Wv   = (const float*)d_in[2];
    const float* bv   = (const float*)d_in[3];
    const float* Wk   = (const float*)d_in[4];
    const float* bk   = (const float*)d_in[5];
    const float* Wq   = (const float*)d_in[6];
    const float* bq   = (const float*)d_in[7];
    float* out = (float*)d_out;

    void *qh, *ql, *kh, *kl, *vf;
    cudaGetSymbolAddress(&qh, g_qh);
    cudaGetSymbolAddress(&ql, g_ql);
    cudaGetSymbolAddress(&kh, g_kh);
    cudaGetSymbolAddress(&kl, g_kl);
    cudaGetSymbolAddress(&vf, g_vf);

    cudaFuncSetAttribute(proj_kernel, cudaFuncAttributeMaxDynamicSharedMemorySize, 65536);
    cudaFuncSetAttribute(attn_mma_kernel, cudaFuncAttributeMaxDynamicSharedMemorySize, SM_BYTES);

    dim3 pg(BB * NN / 64, HH / 64);
    proj_kernel<<<pg, 256, 65536>>>(x, Wv, bv, vf, vf, 1, 1);
    proj_kernel<<<pg, 256, 65536>>>(x, Wk, bk, kh, kl, 0, 0);
    proj_kernel<<<pg, 256, 65536>>>(x, Wq, bq, qh, ql, 0, 0);

    dim3 ag(NN / 128, BB);
    attn_mma_kernel<<<ag, 256, SM_BYTES>>>(mask, out);
}